// round 1
// baseline (speedup 1.0000x reference)
#include <cuda_runtime.h>
#include <math.h>

#define NN 100000
#define EE 1600000
#define ETOT (EE + NN)
#define DIM 128
#define HID 16
#define HEADS 4
#define F1 (HEADS * HID)   // 64
#define NEG 0.2f

// ---------------- scratch (static device globals; no allocation) -------------
__device__ float g_h1[NN * F1];        // layer-1 transformed features
__device__ float g_as1[NN * HEADS];
__device__ float g_ad1[NN * HEADS];
__device__ float g_m1[NN * HEADS];     // segment max
__device__ float g_s1[NN * HEADS];     // segment sum of exp
__device__ float g_agg1[NN * F1];      // unnormalized aggregate
__device__ float g_h3[NN * 2];         // layer-2 transformed features
__device__ float g_as2[NN];
__device__ float g_ad2[NN];
__device__ float g_m2[NN];
__device__ float g_s2[NN];
__device__ float g_agg2[NN * 2];

// ---------------- helpers ----------------------------------------------------
__device__ __forceinline__ void atomicMaxF(float* addr, float v) {
    if (v >= 0.0f) {
        atomicMax((int*)addr, __float_as_int(v));
    } else {
        atomicMin((unsigned int*)addr, (unsigned int)__float_as_int(v));
    }
}

__device__ __forceinline__ void load_edge(const int* __restrict__ ei, int e,
                                          int& s, int& d) {
    if (e < EE) { s = ei[e]; d = ei[EE + e]; }
    else        { s = e - EE; d = e - EE; }   // self loops appended
}

__device__ __forceinline__ float lrelu(float v) {
    return v > 0.0f ? v : NEG * v;
}

// ---------------- kernels ----------------------------------------------------

__global__ void k_init() {
    int i = blockIdx.x * blockDim.x + threadIdx.x;
    if (i < NN * F1) g_agg1[i] = 0.0f;
    if (i < NN * HEADS) { g_m1[i] = -INFINITY; g_s1[i] = 0.0f; }
    if (i < NN) {
        g_m2[i] = -INFINITY; g_s2[i] = 0.0f;
        g_agg2[2 * i] = 0.0f; g_agg2[2 * i + 1] = 0.0f;
    }
}

// h1 = x @ W1 ;  alpha_s1/alpha_d1 per (node, head)
// 8 threads per node, each computes 8 consecutive output channels.
__global__ __launch_bounds__(256) void k_gemm1(
    const float* __restrict__ x, const float* __restrict__ W1,
    const float* __restrict__ asrc, const float* __restrict__ adst) {

    __shared__ float4 Ws[DIM * F1 / 4];   // 2048 float4 = 32KB
    int tid = threadIdx.x;
    #pragma unroll
    for (int i = tid; i < DIM * F1 / 4; i += 256)
        Ws[i] = ((const float4*)W1)[i];
    __syncthreads();

    int nodeLocal = tid >> 3;     // 0..31
    int tj = tid & 7;             // 0..7 -> channels [tj*8, tj*8+8)
    int n = blockIdx.x * 32 + nodeLocal;   // N divisible by 32 (100000/32=3125)
    const float* xr = x + (size_t)n * DIM;

    float4 a0 = make_float4(0.f, 0.f, 0.f, 0.f);
    float4 a1 = make_float4(0.f, 0.f, 0.f, 0.f);
    #pragma unroll 4
    for (int k = 0; k < DIM; k++) {
        float xv = __ldg(xr + k);
        float4 w0 = Ws[k * 16 + tj * 2];
        float4 w1 = Ws[k * 16 + tj * 2 + 1];
        a0.x += xv * w0.x; a0.y += xv * w0.y; a0.z += xv * w0.z; a0.w += xv * w0.w;
        a1.x += xv * w1.x; a1.y += xv * w1.y; a1.z += xv * w1.z; a1.w += xv * w1.w;
    }

    float4* h1p = (float4*)(g_h1 + (size_t)n * F1 + tj * 8);
    h1p[0] = a0; h1p[1] = a1;

    int j0 = tj * 8;
    float ps = a0.x * asrc[j0]     + a0.y * asrc[j0 + 1] +
               a0.z * asrc[j0 + 2] + a0.w * asrc[j0 + 3] +
               a1.x * asrc[j0 + 4] + a1.y * asrc[j0 + 5] +
               a1.z * asrc[j0 + 6] + a1.w * asrc[j0 + 7];
    float pd = a0.x * adst[j0]     + a0.y * adst[j0 + 1] +
               a0.z * adst[j0 + 2] + a0.w * adst[j0 + 3] +
               a1.x * adst[j0 + 4] + a1.y * adst[j0 + 5] +
               a1.z * adst[j0 + 6] + a1.w * adst[j0 + 7];
    ps += __shfl_xor_sync(0xffffffffu, ps, 1);
    pd += __shfl_xor_sync(0xffffffffu, pd, 1);
    if ((tj & 1) == 0) {
        int h = tj >> 1;
        g_as1[n * HEADS + h] = ps;
        g_ad1[n * HEADS + h] = pd;
    }
}

// layer-1 segment max over edges, per (dst, head)
__global__ void k_max1(const int* __restrict__ ei) {
    int e = blockIdx.x * blockDim.x + threadIdx.x;
    if (e >= ETOT) return;
    int s, d; load_edge(ei, e, s, d);
    float4 as = *(const float4*)(g_as1 + s * 4);
    float4 ad = *(const float4*)(g_ad1 + d * 4);
    float e0 = lrelu(as.x + ad.x);
    float e1 = lrelu(as.y + ad.y);
    float e2 = lrelu(as.z + ad.z);
    float e3 = lrelu(as.w + ad.w);
    atomicMaxF(g_m1 + d * 4 + 0, e0);
    atomicMaxF(g_m1 + d * 4 + 1, e1);
    atomicMaxF(g_m1 + d * 4 + 2, e2);
    atomicMaxF(g_m1 + d * 4 + 3, e3);
}

// layer-1 accumulate: agg1[dst] += w * h1[src], s1[dst] += w
// one thread per (edge, group of 4 channels) -> 16 threads/edge
__global__ void k_acc1(const int* __restrict__ ei) {
    int idx = blockIdx.x * blockDim.x + threadIdx.x;
    if (idx >= ETOT * 16) return;
    int e = idx >> 4;
    int g = idx & 15;
    int h = g >> 2;
    int s, d; load_edge(ei, e, s, d);
    float ev = lrelu(g_as1[s * 4 + h] + g_ad1[d * 4 + h]);
    float w = __expf(ev - g_m1[d * 4 + h]);
    if ((g & 3) == 0) atomicAdd(g_s1 + d * 4 + h, w);
    float4 hv = *(const float4*)(g_h1 + (size_t)s * F1 + g * 4);
    float* o = g_agg1 + (size_t)d * F1 + g * 4;
    atomicAdd(o + 0, w * hv.x);
    atomicAdd(o + 1, w * hv.y);
    atomicAdd(o + 2, w * hv.z);
    atomicAdd(o + 3, w * hv.w);
}

// normalize + bias + ELU, then h3 = h2 @ W2 and layer-2 attention logits.
// one warp per node; lane handles channels (lane, lane+32)
__global__ __launch_bounds__(256) void k_l2prep(
    const float* __restrict__ b1, const float* __restrict__ W2,
    const float* __restrict__ as2, const float* __restrict__ ad2) {

    int tid = threadIdx.x;
    int lane = tid & 31;
    int n = blockIdx.x * 8 + (tid >> 5);
    if (n >= NN) return;

    int c0 = lane, c1 = lane + 32;
    float den0 = g_s1[n * 4 + (c0 >> 4)] + 1e-16f;
    float den1 = g_s1[n * 4 + (c1 >> 4)] + 1e-16f;
    float v0 = g_agg1[(size_t)n * F1 + c0] / den0 + b1[c0];
    float v1 = g_agg1[(size_t)n * F1 + c1] / den1 + b1[c1];
    v0 = v0 > 0.0f ? v0 : expm1f(v0);   // ELU(alpha=1)
    v1 = v1 > 0.0f ? v1 : expm1f(v1);

    float p0 = v0 * W2[c0 * 2 + 0] + v1 * W2[c1 * 2 + 0];
    float p1 = v0 * W2[c0 * 2 + 1] + v1 * W2[c1 * 2 + 1];
    #pragma unroll
    for (int o = 16; o > 0; o >>= 1) {
        p0 += __shfl_down_sync(0xffffffffu, p0, o);
        p1 += __shfl_down_sync(0xffffffffu, p1, o);
    }
    if (lane == 0) {
        g_h3[n * 2 + 0] = p0;
        g_h3[n * 2 + 1] = p1;
        g_as2[n] = p0 * as2[0] + p1 * as2[1];
        g_ad2[n] = p0 * ad2[0] + p1 * ad2[1];
    }
}

__global__ void k_max2(const int* __restrict__ ei) {
    int e = blockIdx.x * blockDim.x + threadIdx.x;
    if (e >= ETOT) return;
    int s, d; load_edge(ei, e, s, d);
    float ev = lrelu(g_as2[s] + g_ad2[d]);
    atomicMaxF(g_m2 + d, ev);
}

__global__ void k_acc2(const int* __restrict__ ei) {
    int e = blockIdx.x * blockDim.x + threadIdx.x;
    if (e >= ETOT) return;
    int s, d; load_edge(ei, e, s, d);
    float ev = lrelu(g_as2[s] + g_ad2[d]);
    float w = __expf(ev - g_m2[d]);
    atomicAdd(g_s2 + d, w);
    float2 hv = *(const float2*)(g_h3 + s * 2);
    atomicAdd(g_agg2 + d * 2 + 0, w * hv.x);
    atomicAdd(g_agg2 + d * 2 + 1, w * hv.y);
}

__global__ void k_out(float* __restrict__ out, const float* __restrict__ b2) {
    int i = blockIdx.x * blockDim.x + threadIdx.x;
    if (i >= NN * 2) return;
    int n = i >> 1, j = i & 1;
    out[i] = g_agg2[i] / (g_s2[n] + 1e-16f) + b2[j];
}

// ---------------- launch ------------------------------------------------------
extern "C" void kernel_launch(void* const* d_in, const int* in_sizes, int n_in,
                              void* d_out, int out_size) {
    const float* x    = (const float*)d_in[0];
    const int*   ei   = (const int*)  d_in[1];
    const float* W1   = (const float*)d_in[2];
    const float* as1  = (const float*)d_in[3];
    const float* ad1  = (const float*)d_in[4];
    const float* b1   = (const float*)d_in[5];
    const float* W2   = (const float*)d_in[6];
    const float* as2  = (const float*)d_in[7];
    const float* ad2  = (const float*)d_in[8];
    const float* b2   = (const float*)d_in[9];
    float* out = (float*)d_out;

    const int T = 256;
    k_init<<<(NN * F1 + T - 1) / T, T>>>();
    k_gemm1<<<NN / 32, T>>>(x, W1, as1, ad1);
    k_max1<<<(ETOT + T - 1) / T, T>>>(ei);
    k_acc1<<<(ETOT * 16 + T - 1) / T, T>>>(ei);
    k_l2prep<<<(NN + 7) / 8, T>>>(b1, W2, as2, ad2);
    k_max2<<<(ETOT + T - 1) / T, T>>>(ei);
    k_acc2<<<(ETOT + T - 1) / T, T>>>(ei);
    k_out<<<(NN * 2 + T - 1) / T, T>>>(out, b2);
}